// round 11
// baseline (speedup 1.0000x reference)
#include <cuda_runtime.h>
#include <cstdint>

#define DM 1024
#define NH 16
#define DH 64
#define BB 2
#define SS 2048
#define MT (BB*SS)

// Scratch (device globals; no allocation allowed anywhere)
__device__ float g_qh[MT*DM];   // [B,H,S,DH]
__device__ float g_kh[MT*DM];
__device__ float g_vh[MT*DM];
__device__ float g_at[MT*DM];   // merged-head attention output [B,S,DM]

// ---------------------------------------------------------------------------
__device__ __forceinline__ unsigned tf32r(float x) {
    unsigned u;
    asm("cvt.rna.tf32.f32 %0, %1;" : "=r"(u) : "f"(x));
    return u;
}
__device__ __forceinline__ void mma_tf32(float c[4], const unsigned a[4],
                                         const unsigned b[2]) {
    asm volatile(
        "mma.sync.aligned.m16n8k8.row.col.f32.tf32.tf32.f32 "
        "{%0,%1,%2,%3}, {%4,%5,%6,%7}, {%8,%9}, {%0,%1,%2,%3};"
        : "+f"(c[0]), "+f"(c[1]), "+f"(c[2]), "+f"(c[3])
        : "r"(a[0]), "r"(a[1]), "r"(a[2]), "r"(a[3]), "r"(b[0]), "r"(b[1]));
}

struct GA { const float* A; const float* W; const float* bias; float* out; };
struct G3 { GA g[3]; };

// ---------------------------------------------------------------------------
// TF32 GEMM, double-buffered. out[M,1024] = A @ W + bias.
// Block 128x128, BK=16, 128 threads (4 warps, warp tile 64x64), 2 CTAs/SM.
// blockIdx.z selects one of up to 3 independent (A,W,bias,out) problems.
// ---------------------------------------------------------------------------
__global__ __launch_bounds__(128, 2) void gemm_tf32(G3 P, int split)
{
    __shared__ __align__(16) unsigned As[2][2048];   // [buf][kt2][mt8][lane*4+rg]
    __shared__ __align__(16) unsigned Bs[2][2048];   // [buf][kt2][nt16][lane*2+rg]

    const GA ga = P.g[blockIdx.z];
    const int tid = threadIdx.x, lane = tid & 31, wid = tid >> 5;
    const int g = lane >> 2, t = lane & 3;
    const int bm = blockIdx.y * 128, bn = blockIdx.x * 128;

    // A staging: thread -> (m-tile, row-in-tile, k8-tile); rows (m, m+8), full k8
    const int a_mt = tid >> 4, a_rl = (tid >> 1) & 7, a_kt = tid & 1;
    const unsigned a_base = (a_kt * 8 + a_mt) * 128 + a_rl * 16;
    const float* Aptr = ga.A + (size_t)(bm + a_mt * 16 + a_rl) * DM + a_kt * 8;

    // B staging: thread -> k-row pair (kr, kr+4) for both kt, n-quad
    const int b_kr = tid >> 5;
    const int b_n4 = (tid & 31) << 2;
    const float* Wptr = ga.W + (size_t)b_kr * DM + bn + b_n4;

    const int mt0 = (wid >> 1) * 4, nt0 = (wid & 1) * 8;

    float acc[4][8][4];
    #pragma unroll
    for (int im = 0; im < 4; im++)
        #pragma unroll
        for (int jn = 0; jn < 8; jn++)
            #pragma unroll
            for (int r = 0; r < 4; r++) acc[im][jn][r] = 0.f;

    float4 ra0, ra1, ra2, ra3, rb0, rb1, rb2, rb3;

#define G_LOAD(K0) do {                                                     \
    ra0 = *(const float4*)(Aptr + (K0));                                    \
    ra1 = *(const float4*)(Aptr + (K0) + 4);                                \
    ra2 = *(const float4*)(Aptr + (K0) + 8 * DM);                           \
    ra3 = *(const float4*)(Aptr + (K0) + 8 * DM + 4);                       \
    rb0 = *(const float4*)(Wptr + (size_t)(K0) * DM);                       \
    rb1 = *(const float4*)(Wptr + (size_t)(K0) * DM + 4 * DM);              \
    rb2 = *(const float4*)(Wptr + (size_t)(K0 + 8) * DM);                   \
    rb3 = *(const float4*)(Wptr + (size_t)(K0 + 8) * DM + 4 * DM);          \
} while (0)

#define G_STORE(BUF) do {                                                   \
    float fa0[4] = {ra0.x, ra0.y, ra0.z, ra0.w};                            \
    float fa1[4] = {ra1.x, ra1.y, ra1.z, ra1.w};                            \
    float fa2[4] = {ra2.x, ra2.y, ra2.z, ra2.w};                            \
    float fa3[4] = {ra3.x, ra3.y, ra3.z, ra3.w};                            \
    _Pragma("unroll")                                                       \
    for (int j = 0; j < 4; j++) {                                           \
        uint2 p0 = make_uint2(tf32r(fa0[j]), tf32r(fa2[j]));                \
        *(uint2*)&As[BUF][a_base + j * 4 + 0] = p0;                         \
        uint2 p1 = make_uint2(tf32r(fa1[j]), tf32r(fa3[j]));                \
        *(uint2*)&As[BUF][a_base + j * 4 + 2] = p1;                         \
    }                                                                       \
    float fb0[4] = {rb0.x, rb0.y, rb0.z, rb0.w};                            \
    float fb1[4] = {rb1.x, rb1.y, rb1.z, rb1.w};                            \
    float fb2[4] = {rb2.x, rb2.y, rb2.z, rb2.w};                            \
    float fb3[4] = {rb3.x, rb3.y, rb3.z, rb3.w};                            \
    _Pragma("unroll")                                                       \
    for (int j = 0; j < 4; j++) {                                           \
        int n = b_n4 + j, nt = n >> 3;                                      \
        int ln = (n & 7) * 4 + b_kr;                                        \
        uint2 p0 = make_uint2(tf32r(fb0[j]), tf32r(fb1[j]));                \
        *(uint2*)&Bs[BUF][(0 * 16 + nt) * 64 + ln * 2] = p0;                \
        uint2 p1 = make_uint2(tf32r(fb2[j]), tf32r(fb3[j]));                \
        *(uint2*)&Bs[BUF][(1 * 16 + nt) * 64 + ln * 2] = p1;                \
    }                                                                       \
} while (0)

    G_LOAD(0);
    G_STORE(0);
    __syncthreads();

    for (int kc = 0; kc < 64; kc++) {
        if (kc < 63) G_LOAD((kc + 1) * 16);
        const int buf = kc & 1;
        #pragma unroll
        for (int kt = 0; kt < 2; kt++) {
            unsigned a[4][4], b[8][2];
            #pragma unroll
            for (int im = 0; im < 4; im++)
                *(uint4*)a[im] =
                    *(const uint4*)&As[buf][(kt * 8 + mt0 + im) * 128 + lane * 4];
            #pragma unroll
            for (int jn = 0; jn < 8; jn++)
                *(uint2*)b[jn] =
                    *(const uint2*)&Bs[buf][(kt * 16 + nt0 + jn) * 64 + lane * 2];
            #pragma unroll
            for (int im = 0; im < 4; im++)
                #pragma unroll
                for (int jn = 0; jn < 8; jn++)
                    mma_tf32(acc[im][jn], a[im], b[jn]);
        }
        if (kc < 63) G_STORE((kc + 1) & 1);
        __syncthreads();
    }

    // Epilogue
    #pragma unroll
    for (int im = 0; im < 4; im++) {
        int r0 = bm + (wid >> 1) * 64 + im * 16 + g;
        int r1 = r0 + 8;
        #pragma unroll
        for (int jn = 0; jn < 8; jn++) {
            int col = bn + (wid & 1) * 64 + jn * 8 + t * 2;
            float b0 = ga.bias[col], b1 = ga.bias[col + 1];
            float v00 = acc[im][jn][0] + b0, v01 = acc[im][jn][1] + b1;
            float v10 = acc[im][jn][2] + b0, v11 = acc[im][jn][3] + b1;
            if (split) {
                int h = col >> 6, d = col & 63;
                int b_0 = r0 >> 11, s_0 = r0 & (SS - 1);
                int b_1 = r1 >> 11, s_1 = r1 & (SS - 1);
                float* p0 = ga.out + (((size_t)(b_0 * NH + h)) * SS + s_0) * DH + d;
                float* p1 = ga.out + (((size_t)(b_1 * NH + h)) * SS + s_1) * DH + d;
                p0[0] = v00; p0[1] = v01;
                p1[0] = v10; p1[1] = v11;
            } else {
                float* p0 = ga.out + (size_t)r0 * DM + col;
                float* p1 = ga.out + (size_t)r1 * DM + col;
                p0[0] = v00; p0[1] = v01;
                p1[0] = v10; p1[1] = v11;
            }
        }
    }
#undef G_LOAD
#undef G_STORE
}

// ---------------------------------------------------------------------------
// TF32 flash attention. Block = 128 q x (head, batch), 128 threads = 4 warps,
// each warp owns 32 q rows x 64-key tile. Q fragments live in REGISTERS
// (loaded once); the staged-Q smem region is reused as the P buffer.
// ---------------------------------------------------------------------------
__global__ __launch_bounds__(128) void attn_tf32(const float* __restrict__ mask,
                                                 float* __restrict__ outp)
{
    extern __shared__ __align__(16) unsigned smu[];
    unsigned* Pf = smu;              // [wid4][ktk8][im2][lane*4+rg] = 8192 u32
    unsigned* Kf = smu + 8192;       // [ktd8][ntk8][lane*2+rg]      = 4096
    unsigned* Vf = smu + 12288;      // [ktk8][ntd8][lane*2+rg]      = 4096

    const int tid  = threadIdx.x;
    const int lane = tid & 31, wid = tid >> 5;
    const int g = lane >> 2, t = lane & 3;
    const int q0 = blockIdx.x * 128;
    const int h  = blockIdx.y;
    const int b  = blockIdx.z;
    const float* Qg = g_qh + (size_t)(b * NH + h) * SS * DH;
    const float* Kg = g_kh + (size_t)(b * NH + h) * SS * DH;
    const float* Vg = g_vh + (size_t)(b * NH + h) * SS * DH;
    const int mt0 = wid * 2;

    float o[2][8][4];
    #pragma unroll
    for (int im = 0; im < 2; im++)
        #pragma unroll
        for (int j = 0; j < 8; j++)
            #pragma unroll
            for (int r = 0; r < 4; r++) o[im][j][r] = 0.f;
    float mrow[2][2] = {{-1e30f, -1e30f}, {-1e30f, -1e30f}};
    float lrow[2][2] = {{0.f, 0.f}, {0.f, 0.f}};

    // Stage Q tile (128x64) into Pf region temporarily: row pairs (q, q+8)
    #pragma unroll
    for (int i = 0; i < 8; i++) {
        int idx = i * 128 + tid;
        int dq = (idx & 15) << 2;
        int row_id = idx >> 4;
        int mt = row_id >> 3, rl = row_id & 7;
        const float* p = Qg + (size_t)(q0 + mt * 16 + rl) * DH + dq;
        float4 v0 = *(const float4*)p;
        float4 v1 = *(const float4*)(p + 8 * DH);
        float f0[4] = {v0.x, v0.y, v0.z, v0.w};
        float f1[4] = {v1.x, v1.y, v1.z, v1.w};
        int ktd = dq >> 3;
        int rb = ((dq >> 2) & 1) << 1;
        unsigned* base = &Pf[((ktd * 8 + mt) * 32 + (rl << 2)) * 4 + rb];
        #pragma unroll
        for (int j = 0; j < 4; j++) {
            uint2 pr = make_uint2(tf32r(f0[j]), tf32r(f1[j]));
            *(uint2*)(base + j * 4) = pr;
        }
    }
    __syncthreads();

    // Hoist this warp's Q fragments into registers (reused for all key tiles)
    unsigned qa[2][8][4];
    #pragma unroll
    for (int ktd = 0; ktd < 8; ktd++) {
        *(uint4*)qa[0][ktd] = *(const uint4*)&Pf[((ktd * 8 + mt0) * 32 + lane) * 4];
        *(uint4*)qa[1][ktd] = *(const uint4*)&Pf[((ktd * 8 + mt0 + 1) * 32 + lane) * 4];
    }
    // NOTE: the __syncthreads after K/V staging below orders these reads
    // before any warp's P scatter overwrites Pf.

    for (int k0 = 0; k0 < SS; k0 += 64) {
        // Stage K (64 keys x 64 d): d-pairs (d, d+4)
        #pragma unroll
        for (int i = 0; i < 4; i++) {
            int idx = i * 128 + tid;
            int dq = (idx & 7) << 3;
            int key = idx >> 3;
            const float* p = Kg + (size_t)(k0 + key) * DH + dq;
            float4 v0 = *(const float4*)p;
            float4 v1 = *(const float4*)(p + 4);
            float f0[4] = {v0.x, v0.y, v0.z, v0.w};
            float f1[4] = {v1.x, v1.y, v1.z, v1.w};
            int ktd = dq >> 3, ntk = key >> 3;
            unsigned* base = &Kf[((ktd * 8 + ntk) * 32 + ((key & 7) << 2)) * 2];
            #pragma unroll
            for (int j = 0; j < 4; j++) {
                uint2 pr = make_uint2(tf32r(f0[j]), tf32r(f1[j]));
                *(uint2*)(base + j * 2) = pr;
            }
        }
        // Stage V (64 keys x 64 d): key-pairs (key, key+4)
        #pragma unroll
        for (int i = 0; i < 4; i++) {
            int idx = i * 128 + tid;
            int dq = (idx & 15) << 2;
            int klid = idx >> 4;
            int ktk = klid >> 2, kr = klid & 3;
            const float* p = Vg + (size_t)(k0 + ktk * 8 + kr) * DH + dq;
            float4 v0 = *(const float4*)p;
            float4 v1 = *(const float4*)(p + 4 * DH);
            float f0[4] = {v0.x, v0.y, v0.z, v0.w};
            float f1[4] = {v1.x, v1.y, v1.z, v1.w};
            #pragma unroll
            for (int j = 0; j < 4; j++) {
                int d = dq + j, ntd = d >> 3;
                int ln = ((d & 7) << 2) | kr;
                uint2 pr = make_uint2(tf32r(f0[j]), tf32r(f1[j]));
                *(uint2*)&Vf[((ktk * 8 + ntd) * 32 + ln) * 2] = pr;
            }
        }
        __syncthreads();

        // Scores: 32q x 64k per warp (Q from registers)
        float s[2][8][4];
        #pragma unroll
        for (int im = 0; im < 2; im++)
            #pragma unroll
            for (int j = 0; j < 8; j++)
                #pragma unroll
                for (int r = 0; r < 4; r++) s[im][j][r] = 0.f;

        #pragma unroll
        for (int ktd = 0; ktd < 8; ktd++) {
            #pragma unroll
            for (int nt = 0; nt < 8; nt++) {
                unsigned bk[2];
                *(uint2*)bk = *(const uint2*)&Kf[((ktd * 8 + nt) * 32 + lane) * 2];
                mma_tf32(s[0][nt], qa[0][ktd], bk);
                mma_tf32(s[1][nt], qa[1][ktd], bk);
            }
        }

        // Scale + mask
        #pragma unroll
        for (int im = 0; im < 2; im++) {
            int r0 = q0 + wid * 32 + im * 16 + g;
            int r1 = r0 + 8;
            #pragma unroll
            for (int nt = 0; nt < 8; nt++) {
                int col = k0 + nt * 8 + t * 2;
                float2 mk0 = __ldg((const float2*)(mask + (size_t)r0 * SS + col));
                float2 mk1 = __ldg((const float2*)(mask + (size_t)r1 * SS + col));
                s[im][nt][0] = s[im][nt][0] * 0.125f - 1e9f * mk0.x;
                s[im][nt][1] = s[im][nt][1] * 0.125f - 1e9f * mk0.y;
                s[im][nt][2] = s[im][nt][2] * 0.125f - 1e9f * mk1.x;
                s[im][nt][3] = s[im][nt][3] * 0.125f - 1e9f * mk1.y;
            }
        }

        // Online softmax per (im, row-half); stats shared within lane quad
        #pragma unroll
        for (int im = 0; im < 2; im++) {
            float mx0 = -1e30f, mx1 = -1e30f;
            #pragma unroll
            for (int nt = 0; nt < 8; nt++) {
                mx0 = fmaxf(mx0, fmaxf(s[im][nt][0], s[im][nt][1]));
                mx1 = fmaxf(mx1, fmaxf(s[im][nt][2], s[im][nt][3]));
            }
            mx0 = fmaxf(mx0, __shfl_xor_sync(0xffffffffu, mx0, 1));
            mx0 = fmaxf(mx0, __shfl_xor_sync(0xffffffffu, mx0, 2));
            mx1 = fmaxf(mx1, __shfl_xor_sync(0xffffffffu, mx1, 1));
            mx1 = fmaxf(mx1, __shfl_xor_sync(0xffffffffu, mx1, 2));

            float nm0 = fmaxf(mrow[im][0], mx0), nm1 = fmaxf(mrow[im][1], mx1);
            float al0 = __expf(mrow[im][0] - nm0), al1 = __expf(mrow[im][1] - nm1);
            float sum0 = 0.f, sum1 = 0.f;
            #pragma unroll
            for (int nt = 0; nt < 8; nt++) {
                float p0 = __expf(s[im][nt][0] - nm0);
                float p1 = __expf(s[im][nt][1] - nm0);
                float p2 = __expf(s[im][nt][2] - nm1);
                float p3 = __expf(s[im][nt][3] - nm1);
                s[im][nt][0] = p0; s[im][nt][1] = p1;
                s[im][nt][2] = p2; s[im][nt][3] = p3;
                sum0 += p0 + p1;
                sum1 += p2 + p3;
            }
            sum0 += __shfl_xor_sync(0xffffffffu, sum0, 1);
            sum0 += __shfl_xor_sync(0xffffffffu, sum0, 2);
            sum1 += __shfl_xor_sync(0xffffffffu, sum1, 1);
            sum1 += __shfl_xor_sync(0xffffffffu, sum1, 2);
            lrow[im][0] = lrow[im][0] * al0 + sum0;
            lrow[im][1] = lrow[im][1] * al1 + sum1;
            mrow[im][0] = nm0; mrow[im][1] = nm1;

            #pragma unroll
            for (int nt = 0; nt < 8; nt++) {
                o[im][nt][0] *= al0; o[im][nt][1] *= al0;
                o[im][nt][2] *= al1; o[im][nt][3] *= al1;
            }
        }

        // Scatter P (C-frag) into A-frag layout: per nt, two STS.64
        {
            const int ln0 = g * 4 + ((2 * t) & 3);
            const int rgb = (t >> 1) << 1;
            #pragma unroll
            for (int im = 0; im < 2; im++) {
                #pragma unroll
                for (int nt = 0; nt < 8; nt++) {
                    unsigned* base = &Pf[((wid * 8 + nt) * 2 + im) * 128];
                    uint2 p02 = make_uint2(tf32r(s[im][nt][0]), tf32r(s[im][nt][2]));
                    *(uint2*)&base[ln0 * 4 + rgb] = p02;
                    uint2 p13 = make_uint2(tf32r(s[im][nt][1]), tf32r(s[im][nt][3]));
                    *(uint2*)&base[(ln0 + 1) * 4 + rgb] = p13;
                }
            }
        }
        __syncwarp();

        // PV: A-frag LDS.128 per (ktk, im), B from Vf
        #pragma unroll
        for (int ktk = 0; ktk < 8; ktk++) {
            unsigned ap[2][4];
            *(uint4*)ap[0] = *(const uint4*)&Pf[(((wid * 8 + ktk) * 2 + 0) * 128) + lane * 4];
            *(uint4*)ap[1] = *(const uint4*)&Pf[(((wid * 8 + ktk) * 2 + 1) * 128) + lane * 4];
            #pragma unroll
            for (int ntd = 0; ntd < 8; ntd++) {
                unsigned bv[2];
                *(uint2*)bv = *(const uint2*)&Vf[((ktk * 8 + ntd) * 32 + lane) * 2];
                mma_tf32(o[0][ntd], ap[0], bv);
                mma_tf32(o[1][ntd], ap[1], bv);
            }
        }
        __syncthreads();
    }

    // Epilogue: normalize + write merged-head layout
    #pragma unroll
    for (int im = 0; im < 2; im++) {
        float inv0 = 1.0f / lrow[im][0], inv1 = 1.0f / lrow[im][1];
        int r0 = q0 + wid * 32 + im * 16 + g;
        int r1 = r0 + 8;
        #pragma unroll
        for (int ntd = 0; ntd < 8; ntd++) {
            int col = h * DH + ntd * 8 + t * 2;
            float2 v0 = make_float2(o[im][ntd][0] * inv0, o[im][ntd][1] * inv0);
            float2 v1 = make_float2(o[im][ntd][2] * inv1, o[im][ntd][3] * inv1);
            *(float2*)(outp + ((size_t)b * SS + r0) * DM + col) = v0;
            *(float2*)(outp + ((size_t)b * SS + r1) * DM + col) = v1;
        }
    }
}

// ---------------------------------------------------------------------------
extern "C" void kernel_launch(void* const* d_in, const int* in_sizes, int n_in,
                              void* d_out, int out_size)
{
    const float* q    = (const float*)d_in[0];
    const float* k    = (const float*)d_in[1];
    const float* v    = (const float*)d_in[2];
    const float* mask = (const float*)d_in[3];
    const float* wq   = (const float*)d_in[4];
    const float* bq   = (const float*)d_in[5];
    const float* wk   = (const float*)d_in[6];
    const float* bk   = (const float*)d_in[7];
    const float* wv   = (const float*)d_in[8];
    const float* bv   = (const float*)d_in[9];
    const float* wo   = (const float*)d_in[10];
    const float* bo   = (const float*)d_in[11];

    float *qh, *kh, *vh, *at;
    cudaGetSymbolAddress((void**)&qh, g_qh);
    cudaGetSymbolAddress((void**)&kh, g_kh);
    cudaGetSymbolAddress((void**)&vh, g_vh);
    cudaGetSymbolAddress((void**)&at, g_at);

    const int attn_smem = (8192 + 4096 + 4096) * (int)sizeof(unsigned);  // 64 KB
    cudaFuncSetAttribute(attn_tf32, cudaFuncAttributeMaxDynamicSharedMemorySize,
                         attn_smem);

    // Fused Q/K/V projections (independent problems, z-indexed)
    G3 pqkv;
    pqkv.g[0] = GA{q, wq, bq, qh};
    pqkv.g[1] = GA{k, wk, bk, kh};
    pqkv.g[2] = GA{v, wv, bv, vh};
    dim3 gqkv(DM / 128, MT / 128, 3);
    gemm_tf32<<<gqkv, 128>>>(pqkv, 1);

    dim3 ga(SS / 128, NH, BB);
    attn_tf32<<<ga, 128, attn_smem>>>(mask, at);

    G3 po;
    po.g[0] = GA{at, wo, bo, (float*)d_out};
    po.g[1] = po.g[0];
    po.g[2] = po.g[0];
    dim3 go(DM / 128, MT / 128, 1);
    gemm_tf32<<<go, 128>>>(po, 0);
}

// round 12
// speedup vs baseline: 1.7125x; 1.7125x over previous
#include <cuda_runtime.h>
#include <cstdint>

#define DM 1024
#define NH 16
#define DH 64
#define BB 2
#define SS 2048
#define MT (BB*SS)

// Scratch (device globals; no allocation allowed anywhere)
__device__ float g_qh[MT*DM];    // [B,H,S,DH]
__device__ float g_kh[MT*DM];    // [B,H,S,DH]
__device__ float g_vt[MT*DM];    // [B,H,DH,S]  (V transposed)
__device__ float g_at[MT*DM];    // merged-head attention output [B,S,DM]
__device__ float g_wT[4*DM*DM];  // W^T for wq,wk,wv,wo

// ---------------------------------------------------------------------------
__device__ __forceinline__ unsigned tf32r(float x) {
    unsigned u;
    asm("cvt.rna.tf32.f32 %0, %1;" : "=r"(u) : "f"(x));
    return u;
}
__device__ __forceinline__ void mma_tf32(float c[4], const unsigned a[4],
                                         const unsigned b[2]) {
    asm volatile(
        "mma.sync.aligned.m16n8k8.row.col.f32.tf32.tf32.f32 "
        "{%0,%1,%2,%3}, {%4,%5,%6,%7}, {%8,%9}, {%0,%1,%2,%3};"
        : "+f"(c[0]), "+f"(c[1]), "+f"(c[2]), "+f"(c[3])
        : "r"(a[0]), "r"(a[1]), "r"(a[2]), "r"(a[3]), "r"(b[0]), "r"(b[1]));
}

struct GA { const float* A; const float* W; const float* bias; float* out; int mode; };
struct G3 { GA g[3]; };

// ---------------------------------------------------------------------------
// Weight transpose: wt[n*DM + k] = w[k*DM + n]
// ---------------------------------------------------------------------------
__global__ __launch_bounds__(256) void transp(const float* __restrict__ w,
                                              float* __restrict__ wt)
{
    __shared__ float tl[32][33];
    int x = blockIdx.x * 32 + threadIdx.x;
    int y = blockIdx.y * 32 + threadIdx.y;
    #pragma unroll
    for (int j = 0; j < 32; j += 8)
        tl[threadIdx.y + j][threadIdx.x] = w[(size_t)(y + j) * DM + x];
    __syncthreads();
    int x2 = blockIdx.y * 32 + threadIdx.x;
    int y2 = blockIdx.x * 32 + threadIdx.y;
    #pragma unroll
    for (int j = 0; j < 32; j += 8)
        wt[(size_t)(y2 + j) * DM + x2] = tl[threadIdx.x][threadIdx.y + j];
}

// ---------------------------------------------------------------------------
// TF32 GEMM, double-buffered, conflict-free padded row-major smem.
// out[M,1024] = A[M,1024] @ W + bias, W given TRANSPOSED ([n][k]).
// Block 128x128, BK=16, 128 threads (4 warps, warp tile 64x64), 2 CTAs/SM.
// Smem row stride 20 u32 (16 data + 4 pad): fragment LDS.32 reads hit
// bank g*4+t (+const) = full 32-bank permutation; STS.128 <=2-way.
// mode: 0 = plain [m][n]; 1 = split-head [B,H,S,D]; 2 = split transposed [B,H,D,S].
// ---------------------------------------------------------------------------
__global__ __launch_bounds__(128, 2) void gemm_tf32(G3 P)
{
    __shared__ __align__(16) unsigned As[2][2560];   // [buf][row128][20]
    __shared__ __align__(16) unsigned Bs[2][2560];   // [buf][nrow128][20]

    const GA ga = P.g[blockIdx.z];
    const int tid = threadIdx.x, lane = tid & 31, wid = tid >> 5;
    const int g = lane >> 2, t = lane & 3;
    const int bm = blockIdx.y * 128, bn = blockIdx.x * 128;

    // Staging: thread -> (row = tid>>2 (+p*32), k-quad = (tid&3)*4)
    const int sr = tid >> 2, skq = (tid & 3) << 2;
    const float* Aptr = ga.A + (size_t)(bm + sr) * DM + skq;
    const float* Bptr = ga.W + (size_t)(bn + sr) * DM + skq;   // W^T rows = n
    const unsigned stBase = sr * 20 + skq;

    const int wm = (wid >> 1) * 64, wn = (wid & 1) * 64;
    const unsigned aB = (wm + g) * 20 + t;
    const unsigned bB = (wn + g) * 20 + t;

    float acc[4][8][4];
    #pragma unroll
    for (int im = 0; im < 4; im++)
        #pragma unroll
        for (int jn = 0; jn < 8; jn++)
            #pragma unroll
            for (int r = 0; r < 4; r++) acc[im][jn][r] = 0.f;

    float4 ra[4], rb[4];

#define G_LOAD(K0) do {                                                     \
    _Pragma("unroll")                                                       \
    for (int p = 0; p < 4; p++) {                                           \
        ra[p] = *(const float4*)(Aptr + (size_t)p * 32 * DM + (K0));        \
        rb[p] = *(const float4*)(Bptr + (size_t)p * 32 * DM + (K0));        \
    }                                                                       \
} while (0)

#define G_STORE(BUF) do {                                                   \
    _Pragma("unroll")                                                       \
    for (int p = 0; p < 4; p++) {                                           \
        uint4 ua = make_uint4(tf32r(ra[p].x), tf32r(ra[p].y),               \
                              tf32r(ra[p].z), tf32r(ra[p].w));              \
        *(uint4*)&As[BUF][stBase + p * 640] = ua;                           \
        uint4 ub = make_uint4(tf32r(rb[p].x), tf32r(rb[p].y),               \
                              tf32r(rb[p].z), tf32r(rb[p].w));              \
        *(uint4*)&Bs[BUF][stBase + p * 640] = ub;                           \
    }                                                                       \
} while (0)

    G_LOAD(0);
    G_STORE(0);
    __syncthreads();

    for (int kc = 0; kc < 64; kc++) {
        if (kc < 63) G_LOAD((kc + 1) * 16);
        const int buf = kc & 1;
        #pragma unroll
        for (int kt = 0; kt < 2; kt++) {
            unsigned a[4][4], b[8][2];
            #pragma unroll
            for (int im = 0; im < 4; im++) {
                unsigned base = aB + im * 320 + kt * 8;
                a[im][0] = As[buf][base];
                a[im][1] = As[buf][base + 160];
                a[im][2] = As[buf][base + 4];
                a[im][3] = As[buf][base + 164];
            }
            #pragma unroll
            for (int jn = 0; jn < 8; jn++) {
                unsigned base = bB + jn * 160 + kt * 8;
                b[jn][0] = Bs[buf][base];
                b[jn][1] = Bs[buf][base + 4];
            }
            #pragma unroll
            for (int im = 0; im < 4; im++)
                #pragma unroll
                for (int jn = 0; jn < 8; jn++)
                    mma_tf32(acc[im][jn], a[im], b[jn]);
        }
        if (kc < 63) G_STORE((kc + 1) & 1);
        __syncthreads();
    }

    // Epilogue
    #pragma unroll
    for (int im = 0; im < 4; im++) {
        int r0 = bm + wm + im * 16 + g;
        int r1 = r0 + 8;
        #pragma unroll
        for (int jn = 0; jn < 8; jn++) {
            int col = bn + wn + jn * 8 + t * 2;
            float b0 = ga.bias[col], b1 = ga.bias[col + 1];
            float v00 = acc[im][jn][0] + b0, v01 = acc[im][jn][1] + b1;
            float v10 = acc[im][jn][2] + b0, v11 = acc[im][jn][3] + b1;
            if (ga.mode == 0) {
                float* p0 = ga.out + (size_t)r0 * DM + col;
                float* p1 = ga.out + (size_t)r1 * DM + col;
                p0[0] = v00; p0[1] = v01;
                p1[0] = v10; p1[1] = v11;
            } else {
                int h = col >> 6, d = col & 63;
                int b_0 = r0 >> 11, s_0 = r0 & (SS - 1);
                int b_1 = r1 >> 11, s_1 = r1 & (SS - 1);
                if (ga.mode == 1) {
                    float* p0 = ga.out + (((size_t)(b_0 * NH + h)) * SS + s_0) * DH + d;
                    float* p1 = ga.out + (((size_t)(b_1 * NH + h)) * SS + s_1) * DH + d;
                    p0[0] = v00; p0[1] = v01;
                    p1[0] = v10; p1[1] = v11;
                } else {   // mode 2: [B,H,D,S] (V transposed)
                    float* base0 = ga.out + ((size_t)(b_0 * NH + h) * DH + d) * SS + s_0;
                    float* base1 = ga.out + ((size_t)(b_1 * NH + h) * DH + d) * SS + s_1;
                    base0[0] = v00; base0[SS] = v01;
                    base1[0] = v10; base1[SS] = v11;
                }
            }
        }
    }
#undef G_LOAD
#undef G_STORE
}

// ---------------------------------------------------------------------------
// TF32 flash attention, conflict-free padded layouts (stride 68 u32).
// Block = 128 q x (head, batch), 128 threads = 4 warps, warp = 32q x 64k tile.
// Q staged once -> fragments hoisted to registers; Q region aliased as the
// per-warp P buffer (row-major, C-frag stores 2-way, A-frag reads clean).
// K staged [key][d]; V read from pre-transposed g_vt and staged [d][key].
// ---------------------------------------------------------------------------
__global__ __launch_bounds__(128) void attn_tf32(const float* __restrict__ mask,
                                                 float* __restrict__ outp)
{
    extern __shared__ __align__(16) unsigned smu[];
    unsigned* Ps  = smu;              // Q stage, then per-warp P: 128*68 = 8704
    unsigned* Ks  = smu + 8704;       // [key64][68]                       4352
    unsigned* Vts = smu + 13056;      // [d64][68]                          4352

    const int tid  = threadIdx.x;
    const int lane = tid & 31, wid = tid >> 5;
    const int g = lane >> 2, t = lane & 3;
    const int q0 = blockIdx.x * 128;
    const int h  = blockIdx.y;
    const int b  = blockIdx.z;
    const float* Qg  = g_qh + (size_t)(b * NH + h) * SS * DH;
    const float* Kg  = g_kh + (size_t)(b * NH + h) * SS * DH;
    const float* Vtg = g_vt + (size_t)(b * NH + h) * DH * SS;

    float o[2][8][4];
    #pragma unroll
    for (int im = 0; im < 2; im++)
        #pragma unroll
        for (int j = 0; j < 8; j++)
            #pragma unroll
            for (int r = 0; r < 4; r++) o[im][j][r] = 0.f;
    float mrow[2][2] = {{-1e30f, -1e30f}, {-1e30f, -1e30f}};
    float lrow[2][2] = {{0.f, 0.f}, {0.f, 0.f}};

    // Stage Q tile (128 x 64) row-major stride 68
    {
        const int dq = (tid & 15) << 2, qr = tid >> 4;
        #pragma unroll
        for (int i = 0; i < 16; i++) {
            int q = qr + i * 8;
            float4 v = *(const float4*)(Qg + (size_t)(q0 + q) * DH + dq);
            uint4 u = make_uint4(tf32r(v.x), tf32r(v.y), tf32r(v.z), tf32r(v.w));
            *(uint4*)&Ps[q * 68 + dq] = u;
        }
    }
    __syncthreads();

    // Hoist warp's Q fragments (reads from warp's own 32-row band)
    unsigned qa[2][8][4];
    {
        const unsigned qB = (wid * 32 + g) * 68 + t;
        #pragma unroll
        for (int ktd = 0; ktd < 8; ktd++)
            #pragma unroll
            for (int im = 0; im < 2; im++) {
                unsigned base = qB + im * 1088 + ktd * 8;
                qa[im][ktd][0] = Ps[base];
                qa[im][ktd][1] = Ps[base + 544];
                qa[im][ktd][2] = Ps[base + 4];
                qa[im][ktd][3] = Ps[base + 548];
            }
    }

    const unsigned pW = wid * 2176;           // per-warp P base (32 rows x 68)
    const unsigned kB = g * 68 + t;

    for (int k0 = 0; k0 < SS; k0 += 64) {
        // Stage K [key][d] and V^T [d][key], stride 68
        {
            const int cq = (tid & 15) << 2, rr = tid >> 4;
            #pragma unroll
            for (int i = 0; i < 8; i++) {
                int row = rr + i * 8;
                float4 kv = *(const float4*)(Kg + (size_t)(k0 + row) * DH + cq);
                uint4 uk = make_uint4(tf32r(kv.x), tf32r(kv.y), tf32r(kv.z), tf32r(kv.w));
                *(uint4*)&Ks[row * 68 + cq] = uk;
                float4 vv = *(const float4*)(Vtg + (size_t)row * SS + k0 + cq);
                uint4 uv = make_uint4(tf32r(vv.x), tf32r(vv.y), tf32r(vv.z), tf32r(vv.w));
                *(uint4*)&Vts[row * 68 + cq] = uv;
            }
        }
        __syncthreads();

        // Scores: 32q x 64k per warp
        float s[2][8][4];
        #pragma unroll
        for (int im = 0; im < 2; im++)
            #pragma unroll
            for (int j = 0; j < 8; j++)
                #pragma unroll
                for (int r = 0; r < 4; r++) s[im][j][r] = 0.f;

        #pragma unroll
        for (int ktd = 0; ktd < 8; ktd++) {
            #pragma unroll
            for (int nt = 0; nt < 8; nt++) {
                unsigned bk[2];
                unsigned base = kB + nt * 544 + ktd * 8;
                bk[0] = Ks[base];
                bk[1] = Ks[base + 4];
                mma_tf32(s[0][nt], qa[0][ktd], bk);
                mma_tf32(s[1][nt], qa[1][ktd], bk);
            }
        }

        // Scale + mask
        #pragma unroll
        for (int im = 0; im < 2; im++) {
            int r0 = q0 + wid * 32 + im * 16 + g;
            int r1 = r0 + 8;
            #pragma unroll
            for (int nt = 0; nt < 8; nt++) {
                int col = k0 + nt * 8 + t * 2;
                float2 mk0 = __ldg((const float2*)(mask + (size_t)r0 * SS + col));
                float2 mk1 = __ldg((const float2*)(mask + (size_t)r1 * SS + col));
                s[im][nt][0] = s[im][nt][0] * 0.125f - 1e9f * mk0.x;
                s[im][nt][1] = s[im][nt][1] * 0.125f - 1e9f * mk0.y;
                s[im][nt][2] = s[im][nt][2] * 0.125f - 1e9f * mk1.x;
                s[im][nt][3] = s[im][nt][3] * 0.125f - 1e9f * mk1.y;
            }
        }

        // Online softmax per (im, row-half); stats shared within lane quad
        #pragma unroll
        for (int im = 0; im < 2; im++) {
            float mx0 = -1e30f, mx1 = -1e30f;
            #pragma unroll
            for (int nt = 0; nt < 8; nt++) {
                mx0 = fmaxf(mx0, fmaxf(s[im][nt][0], s[im][nt][1]));
                mx1 = fmaxf(mx1, fmaxf(s[im][nt][2], s[im][nt][3]));
            }
            mx0 = fmaxf(mx0, __shfl_xor_sync(0xffffffffu, mx0, 1));
            mx0 = fmaxf(mx0, __shfl_xor_sync(0xffffffffu, mx0, 2));
            mx1 = fmaxf(mx1, __shfl_xor_sync(0xffffffffu, mx1, 1));
            mx1 = fmaxf(mx1, __shfl_xor_sync(0xffffffffu, mx1, 2));

            float nm0 = fmaxf(mrow[im][0], mx0), nm1 = fmaxf(mrow[im][1], mx1);
            float al0 = __expf(mrow[im][0] - nm0), al1 = __expf(mrow[im][1] - nm1);
            float sum0 = 0.f, sum1 = 0.f;
            #pragma unroll
            for (int nt = 0; nt < 8; nt++) {
                float p0 = __expf(s[im][nt][0] - nm0);
                float p1 = __expf(s[im][nt][1] - nm0);
                float p2 = __expf(s[im][nt][2] - nm1);
                float p3 = __expf(s[im][nt][3] - nm1);
                s[im][nt][0] = p0; s[im][nt][1] = p1;
                s[im][nt][2] = p2; s[im][nt][3] = p3;
                sum0 += p0 + p1;
                sum1 += p2 + p3;
            }
            sum0 += __shfl_xor_sync(0xffffffffu, sum0, 1);
            sum0 += __shfl_xor_sync(0xffffffffu, sum0, 2);
            sum1 += __shfl_xor_sync(0xffffffffu, sum1, 1);
            sum1 += __shfl_xor_sync(0xffffffffu, sum1, 2);
            lrow[im][0] = lrow[im][0] * al0 + sum0;
            lrow[im][1] = lrow[im][1] * al1 + sum1;
            mrow[im][0] = nm0; mrow[im][1] = nm1;

            #pragma unroll
            for (int nt = 0; nt < 8; nt++) {
                o[im][nt][0] *= al0; o[im][nt][1] *= al0;
                o[im][nt][2] *= al1; o[im][nt][3] *= al1;
            }
        }

        // Store P row-major into warp's own band: (c0,c1)->row, (c2,c3)->row+8
        #pragma unroll
        for (int im = 0; im < 2; im++) {
            #pragma unroll
            for (int nt = 0; nt < 8; nt++) {
                unsigned idx = pW + (im * 16 + g) * 68 + nt * 8 + t * 2;
                uint2 p01 = make_uint2(tf32r(s[im][nt][0]), tf32r(s[im][nt][1]));
                *(uint2*)&Ps[idx] = p01;
                uint2 p23 = make_uint2(tf32r(s[im][nt][2]), tf32r(s[im][nt][3]));
                *(uint2*)&Ps[idx + 544] = p23;
            }
        }
        __syncwarp();

        // PV: A-frag of P (clean LDS.32 gather), B = V^T tiles
        const unsigned pA = pW + g * 68 + t;
        #pragma unroll
        for (int ktk = 0; ktk < 8; ktk++) {
            unsigned ap[2][4];
            #pragma unroll
            for (int im = 0; im < 2; im++) {
                unsigned base = pA + im * 1088 + ktk * 8;
                ap[im][0] = Ps[base];
                ap[im][1] = Ps[base + 544];
                ap[im][2] = Ps[base + 4];
                ap[im][3] = Ps[base + 548];
            }
            #pragma unroll
            for (int ntd = 0; ntd < 8; ntd++) {
                unsigned bv[2];
                unsigned base = kB + ntd * 544 + ktk * 8;
                bv[0] = Vts[base];
                bv[1] = Vts[base + 4];
                mma_tf32(o[0][ntd], ap[0], bv);
                mma_tf32(o[1][ntd], ap[1], bv);
            }
        }
        __syncthreads();
    }

    // Epilogue: normalize + write merged-head layout
    #pragma unroll
    for (int im = 0; im < 2; im++) {
        float inv0 = 1.0f / lrow[im][0], inv1 = 1.0f / lrow[im][1];
        int r0 = q0 + wid * 32 + im * 16 + g;
        int r1 = r0 + 8;
        #pragma unroll
        for (int ntd = 0; ntd < 8; ntd++) {
            int col = h * DH + ntd * 8 + t * 2;
            float2 v0 = make_float2(o[im][ntd][0] * inv0, o[im][ntd][1] * inv0);
            float2 v1 = make_float2(o[im][ntd][2] * inv1, o[im][ntd][3] * inv1);
            *(float2*)(outp + ((size_t)b * SS + r0) * DM + col) = v0;
            *(float2*)(outp + ((size_t)b * SS + r1) * DM + col) = v1;
        }
    }
}

// ---------------------------------------------------------------------------
extern "C" void kernel_launch(void* const* d_in, const int* in_sizes, int n_in,
                              void* d_out, int out_size)
{
    const float* q    = (const float*)d_in[0];
    const float* k    = (const float*)d_in[1];
    const float* v    = (const float*)d_in[2];
    const float* mask = (const float*)d_in[3];
    const float* wq   = (const float*)d_in[4];
    const float* bq   = (const float*)d_in[5];
    const float* wk   = (const float*)d_in[6];
    const float* bk   = (const float*)d_in[7];
    const float* wv   = (const float*)d_in[8];
    const float* bv   = (const float*)d_in[9];
    const float* wo   = (const float*)d_in[10];
    const float* bo   = (const float*)d_in[11];

    float *qh, *kh, *vt, *at, *wT;
    cudaGetSymbolAddress((void**)&qh, g_qh);
    cudaGetSymbolAddress((void**)&kh, g_kh);
    cudaGetSymbolAddress((void**)&vt, g_vt);
    cudaGetSymbolAddress((void**)&at, g_at);
    cudaGetSymbolAddress((void**)&wT, g_wT);

    const int attn_smem = (8704 + 4352 + 4352) * (int)sizeof(unsigned);  // ~68 KB
    cudaFuncSetAttribute(attn_tf32, cudaFuncAttributeMaxDynamicSharedMemorySize,
                         attn_smem);

    // Transpose weights once per call
    dim3 tb(32, 8), tg(32, 32);
    transp<<<tg, tb>>>(wq, wT + 0 * DM * DM);
    transp<<<tg, tb>>>(wk, wT + 1 * DM * DM);
    transp<<<tg, tb>>>(wv, wT + 2 * DM * DM);
    transp<<<tg, tb>>>(wo, wT + 3 * DM * DM);

    // Fused Q/K/V projections (V written transposed)
    G3 pqkv;
    pqkv.g[0] = GA{q, wT + 0 * DM * DM, bq, qh, 1};
    pqkv.g[1] = GA{k, wT + 1 * DM * DM, bk, kh, 1};
    pqkv.g[2] = GA{v, wT + 2 * DM * DM, bv, vt, 2};
    dim3 gqkv(DM / 128, MT / 128, 3);
    gemm_tf32<<<gqkv, 128>>>(pqkv);

    dim3 ga(SS / 128, NH, BB);
    attn_tf32<<<ga, 128, attn_smem>>>(mask, at);

    G3 po;
    po.g[0] = GA{at, wT + 3 * DM * DM, bo, (float*)d_out, 0};
    po.g[1] = po.g[0];
    po.g[2] = po.g[0];
    dim3 go(DM / 128, MT / 128, 1);
    gemm_tf32<<<go, 128>>>(po);
}